// round 17
// baseline (speedup 1.0000x reference)
#include <cuda_runtime.h>
#include <cuda_bf16.h>
#include <cstdint>

// SeparationLoss: mean over B of sum_{i!=j} max(0, thr2 - ||kp_i - kp_j||^2)
// Input: batched_kps [B, 17, 3] f32 (B = 131072). Output: scalar f32.
//
// R17: warp-specialized split-tile pipeline. Block owns rows [128b, 128b+128)
// as two 64-row half-tiles with separate bulk copies + mbarriers, both issued
// at t=0. Warps 0-1 compute half-A (wait mbA only), warps 2-3 half-B: compute
// starts on first 13KB arrival, no block-wide wait. Core = R9 two-pass Gram
// tiling (proven 64 regs, no spill) -> 8 blocks/SM, 32 warps/SM, grid 1024 =
// one wave. Fused last-block-done reduction.

#define J 17
#define ROW_F 51                    // 17*3 floats per row
#define HALF_ROWS 64
#define THREADS 128
#define HALF_BYTES (HALF_ROWS * ROW_F * 4)    // 13056
#define NBLOCKS_MAX 8192

__device__ __align__(16) float g_partials[NBLOCKS_MAX];
__device__ unsigned int g_done_count;   // zero-init; inc wraps -> self-resets per run

__device__ __forceinline__ uint32_t smem_u32(const void* p) {
    uint32_t a;
    asm("{ .reg .u64 t; cvta.to.shared.u64 t, %1; cvt.u32.u64 %0, t; }"
        : "=r"(a) : "l"(p));
    return a;
}

__device__ __forceinline__ void mbar_wait0(uint32_t mb) {
    uint32_t done;
    asm volatile(
        "{\n\t.reg .pred p;\n\t"
        "mbarrier.try_wait.parity.acquire.cta.shared::cta.b64 p, [%1], 0;\n\t"
        "selp.b32 %0, 1, 0, p;\n\t}"
        : "=r"(done) : "r"(mb) : "memory");
    if (!done) {
        asm volatile(
            "{\n\t.reg .pred P1;\n\t"
            "W_%=:\n\t"
            "mbarrier.try_wait.parity.acquire.cta.shared::cta.b64 P1, [%0], 0, 0x989680;\n\t"
            "@P1 bra.uni D_%=;\n\t"
            "bra.uni W_%=;\n\t"
            "D_%=:\n\t}"
            :: "r"(mb) : "memory");
    }
}

__device__ __forceinline__ void issue_bulk(uint32_t mb, uint32_t dst,
                                           const float* gsrc) {
    asm volatile("mbarrier.arrive.expect_tx.shared.b64 _, [%0], %1;"
                 :: "r"(mb), "r"((uint32_t)HALF_BYTES) : "memory");
    asm volatile(
        "cp.async.bulk.shared::cta.global.mbarrier::complete_tx::bytes "
        "[%0], [%1], %2, [%3];"
        :: "r"(dst), "l"(gsrc), "r"((uint32_t)HALF_BYTES), "r"(mb)
        : "memory");
}

// Two-pass Gram-identity pair sum for one row (R9 core: peak regs ~55, fits
// the 64-reg budget at 8 blocks/SM without spilling).
__device__ __forceinline__ float row_pairs(const float* __restrict__ rp) {
    float a0 = 0.0f, a1 = 0.0f;
    int k = 0;

    // ---- pass 1: joints 0..8 resident ----
    {
        float p[27];
        float g[9];
        #pragma unroll
        for (int c = 0; c < 27; c++) p[c] = rp[c];
        #pragma unroll
        for (int i = 0; i < 9; i++) {
            float x = p[3*i], y = p[3*i+1], z = p[3*i+2];
            float r = fmaf(z, z, fmaf(y, y, x * x));
            g[i] = fmaf(r, -0.5f, 0.0025f);      // 0.25*thr2; FFMA-imm
        }
        #pragma unroll
        for (int i = 0; i < 9; i++)
            #pragma unroll
            for (int j = i + 1; j < 9; j++) {
                float w = g[i] + g[j];
                float d = fmaf(p[3*i+2], p[3*j+2],
                          fmaf(p[3*i+1], p[3*j+1],
                          fmaf(p[3*i  ], p[3*j  ], w)));
                float h = fmaxf(d, 0.0f);
                if (k & 1) a1 += h; else a0 += h;
                k++;
            }
        // cross: stream joints 9..16 from SMEM
        #pragma unroll
        for (int jj = 9; jj < J; jj++) {
            float qx = rp[3*jj], qy = rp[3*jj+1], qz = rp[3*jj+2];
            float qr = fmaf(qz, qz, fmaf(qy, qy, qx * qx));
            float qg = fmaf(qr, -0.5f, 0.0025f);
            #pragma unroll
            for (int i = 0; i < 9; i++) {
                float w = g[i] + qg;
                float d = fmaf(p[3*i+2], qz,
                          fmaf(p[3*i+1], qy,
                          fmaf(p[3*i  ], qx, w)));
                float h = fmaxf(d, 0.0f);
                if (k & 1) a1 += h; else a0 += h;
                k++;
            }
        }
    }
    // ---- pass 2: joints 9..16 resident ----
    {
        float p[24];
        float g[8];
        #pragma unroll
        for (int c = 0; c < 24; c++) p[c] = rp[27 + c];
        #pragma unroll
        for (int i = 0; i < 8; i++) {
            float x = p[3*i], y = p[3*i+1], z = p[3*i+2];
            float r = fmaf(z, z, fmaf(y, y, x * x));
            g[i] = fmaf(r, -0.5f, 0.0025f);
        }
        #pragma unroll
        for (int i = 0; i < 8; i++)
            #pragma unroll
            for (int j = i + 1; j < 8; j++) {
                float w = g[i] + g[j];
                float d = fmaf(p[3*i+2], p[3*j+2],
                          fmaf(p[3*i+1], p[3*j+1],
                          fmaf(p[3*i  ], p[3*j  ], w)));
                float h = fmaxf(d, 0.0f);
                if (k & 1) a1 += h; else a0 += h;
                k++;
            }
    }
    return a0 + a1;
}

__global__ __launch_bounds__(THREADS, 8)   // 64-reg cap (R9-proven); 8 blocks/SM
void sep_loss_fused(const float* __restrict__ kps, int B, int grid,
                    float invB, float* __restrict__ out) {
    __shared__ __align__(16) float sA[HALF_ROWS * ROW_F];   // 13056 B
    __shared__ __align__(16) float sB[HALF_ROWS * ROW_F];   // 13056 B
    __shared__ __align__(8)  unsigned long long mbarA, mbarB;
    __shared__ float wsum[THREADS / 32];
    __shared__ bool  isLast;

    const int tid = threadIdx.x;
    const int blk = blockIdx.x;
    const int rowBaseA = blk * 2 * HALF_ROWS;             // rows [.., +64)
    const int rowBaseB = rowBaseA + HALF_ROWS;            // rows [+64, +128)
    const int rowsA = min(HALF_ROWS, max(0, B - rowBaseA));
    const int rowsB = min(HALF_ROWS, max(0, B - rowBaseB));
    const uint32_t mbA = smem_u32(&mbarA), mbB = smem_u32(&mbarB);

    if (tid == 0) {
        asm volatile("mbarrier.init.shared.b64 [%0], 1;" :: "r"(mbA) : "memory");
        asm volatile("mbarrier.init.shared.b64 [%0], 1;" :: "r"(mbB) : "memory");
    }
    __syncthreads();

    // ---- both half-tile copies at t=0 ----
    if (tid == 0) {
        if (rowsA == HALF_ROWS)
            issue_bulk(mbA, smem_u32(sA), kps + (size_t)rowBaseA * ROW_F);
        if (rowsB == HALF_ROWS)
            issue_bulk(mbB, smem_u32(sB), kps + (size_t)rowBaseB * ROW_F);
    }
    __syncthreads();   // ensure issue precedes any manual-staging writes below

    // ---- warp specialization: warps 0-1 -> half A, warps 2-3 -> half B ----
    const bool halfA = tid < 64;
    const int  row   = tid & 63;
    float acc = 0.0f;

    if (halfA) {
        if (rowsA == HALF_ROWS) {
            mbar_wait0(mbA);
        } else if (rowsA > 0) {
            const float* src = kps + (size_t)rowBaseA * ROW_F;
            for (int i = row; i < rowsA * ROW_F; i += 64) sA[i] = src[i];
            __syncwarp();
            asm volatile("bar.sync 1, 64;" ::: "memory");   // warps 0-1 only
        }
        if (row < rowsA) acc = row_pairs(sA + row * ROW_F);
    } else {
        if (rowsB == HALF_ROWS) {
            mbar_wait0(mbB);
        } else if (rowsB > 0) {
            const float* src = kps + (size_t)rowBaseB * ROW_F;
            for (int i = row; i < rowsB * ROW_F; i += 64) sB[i] = src[i];
            __syncwarp();
            asm volatile("bar.sync 2, 64;" ::: "memory");   // warps 2-3 only
        }
        if (row < rowsB) acc = row_pairs(sB + row * ROW_F);
    }

    // hinge = 2*max(0,d); ordered pairs double again -> x4
    acc *= 4.0f;

    // ---- deterministic block reduction (4 warps) ----
    #pragma unroll
    for (int off = 16; off > 0; off >>= 1)
        acc += __shfl_down_sync(0xFFFFFFFFu, acc, off);
    if ((tid & 31) == 0) wsum[tid >> 5] = acc;
    __syncthreads();

    if (tid == 0) {
        g_partials[blk] = (wsum[0] + wsum[1]) + (wsum[2] + wsum[3]);
        // release-inc orders the store; wraps to 0 at grid-1 (replay-safe)
        unsigned int c;
        asm volatile("atom.acq_rel.gpu.global.inc.u32 %0, [%1], %2;"
                     : "=r"(c)
                     : "l"(&g_done_count), "r"((unsigned int)(grid - 1))
                     : "memory");
        isLast = (c == (unsigned int)(grid - 1));
    }
    __syncthreads();

    // ---- last block: vectorized fixed-order final reduction ----
    if (isLast) {
        float v = 0.0f;
        const int nvec = grid >> 2;               // 256 for grid=1024
        const float4* gp = reinterpret_cast<const float4*>(g_partials);
        #pragma unroll 2
        for (int i = tid; i < nvec; i += THREADS) {
            float4 f = gp[i];
            v += (f.x + f.y) + (f.z + f.w);
        }
        for (int i = (nvec << 2) + tid; i < grid; i += THREADS)
            v += g_partials[i];
        #pragma unroll
        for (int off = 16; off > 0; off >>= 1)
            v += __shfl_down_sync(0xFFFFFFFFu, v, off);
        if ((tid & 31) == 0) wsum[tid >> 5] = v;
        __syncthreads();
        if (tid == 0)
            out[0] = ((wsum[0] + wsum[1]) + (wsum[2] + wsum[3])) * invB;
    }
}

extern "C" void kernel_launch(void* const* d_in, const int* in_sizes, int n_in,
                              void* d_out, int out_size) {
    const float* kps = (const float*)d_in[0];
    const int B = in_sizes[0] / ROW_F;
    const int grid = (B + 2 * HALF_ROWS - 1) / (2 * HALF_ROWS);  // 1024

    sep_loss_fused<<<grid, THREADS>>>(kps, B, grid, 1.0f / (float)B,
                                      (float*)d_out);
}